// round 17
// baseline (speedup 1.0000x reference)
#include <cuda_runtime.h>
#include <cuda_fp16.h>
#include <cstdint>

// DigitCapsules dynamic routing, GB300 sm_103a
// B=256, C=10, I=1152, DI=8, DO=16, 3 routing iterations.
//
// R17: u_hat layout changed to [b][i][c][d] (one capsule's 10 classes
// contiguous, 320 B). route: warp-internal softmax -- lane = (d-half, class),
// one LDG.128 per capsule covers all classes, dot combined via shfl_xor(16),
// Z via 4-round butterfly over classes padded to 16. NO block barrier in the
// capsule loop (R16 showed the per-tile 10-warp barrier convoy was ~44us of
// the 52; barrier-free streaming costs ~4us). Cross-warp s-reduction: smem +
// 2 barriers per ITERATION. uhat: R15 compute verbatim, new output index.

#define BSZ  256
#define CCL  10
#define ICAP 1152
#define DOV  16
#define DIV  8

#define ITILE 16
#define NTIL  (ICAP / ITILE)
#define BCH   32
#define KSTR  20
#define ISTR  164

typedef unsigned long long ull;

__device__ __align__(256) __half g_uhat[(size_t)BSZ * ICAP * CCL * DOV]; // 94.4 MB

// ---------------- packed f32x2 helpers ------------------
static __device__ __forceinline__ ull pack2(float x, float y) {
    ull r; asm("mov.b64 %0, {%1, %2};" : "=l"(r) : "f"(x), "f"(y)); return r;
}
static __device__ __forceinline__ void unpack2(ull v, float& x, float& y) {
    asm("mov.b64 {%0, %1}, %2;" : "=f"(x), "=f"(y) : "l"(v));
}
static __device__ __forceinline__ ull fma2(ull a, ull b, ull c) {
    ull d; asm("fma.rn.f32x2 %0, %1, %2, %3;" : "=l"(d) : "l"(a), "l"(b), "l"(c));
    return d;
}
static __device__ __forceinline__ unsigned int pack_h2(float a, float b) {
    __half2 h = __floats2half2_rn(a, b);
    return *reinterpret_cast<unsigned int*>(&h);
}

// ---------------------------------------------------------------------------
// K_uhat (R15 compute verbatim; output layout [b][i][c][d]).
// grid = 576 (72 i-tiles x 8 b-chunks), 256 threads = (b-pair, i).
// ---------------------------------------------------------------------------
__global__ __launch_bounds__(256) void uhat_kernel(
    const float* __restrict__ x, const float* __restrict__ W)
{
    __shared__ float Wst[ITILE * ISTR];

    const int i0 = (blockIdx.x >> 3) * ITILE;
    const int b0 = (blockIdx.x & 7) * BCH;
    const int t  = threadIdx.x;
    const int bg = t >> 4;
    const int i  = t & 15;
    const int gi = i0 + i;
    const int bA = b0 + 2 * bg;

    float xr[2][8];
    #pragma unroll
    for (int p = 0; p < 2; p++) {
        const float4* xp = reinterpret_cast<const float4*>(
            x + (size_t)(bA + p) * (ICAP * DIV) + (size_t)gi * DIV);
        float4 a = xp[0], bq = xp[1];
        xr[p][0] = a.x;  xr[p][1] = a.y;  xr[p][2] = a.z;  xr[p][3] = a.w;
        xr[p][4] = bq.x; xr[p][5] = bq.y; xr[p][6] = bq.z; xr[p][7] = bq.w;
    }

    #pragma unroll 1
    for (int c = 0; c < CCL; c++) {
        __syncthreads();
        for (int e = t; e < ITILE * DOV * DIV; e += 256) {
            int ie = e >> 7;
            int dk = e & 127;
            int d  = dk >> 3, k = dk & 7;
            Wst[ie * ISTR + k * KSTR + d] =
                W[(size_t)c * (ICAP * DOV * DIV) + (size_t)(i0 + ie) * 128 + dk];
        }
        __syncthreads();

        #pragma unroll
        for (int p = 0; p < 2; p++) {
            ull acc[8];
            #pragma unroll
            for (int j = 0; j < 8; j++) acc[j] = 0ULL;

            #pragma unroll
            for (int k = 0; k < DIV; k++) {
                const ull xx = pack2(xr[p][k], xr[p][k]);
                const ull* wk = reinterpret_cast<const ull*>(
                    Wst + i * ISTR + k * KSTR);
                #pragma unroll
                for (int j = 0; j < 8; j++) acc[j] = fma2(wk[j], xx, acc[j]);
            }

            unsigned int h[8];
            #pragma unroll
            for (int j = 0; j < 8; j++) {
                float lo, hi; unpack2(acc[j], lo, hi);
                h[j] = pack_h2(lo, hi);
            }
            // NEW layout: [b][i][c][d]
            __half* o = g_uhat
                + (((size_t)(bA + p) * ICAP + gi) * CCL + c) * DOV;
            *reinterpret_cast<uint4*>(o)     = make_uint4(h[0], h[1], h[2], h[3]);
            *reinterpret_cast<uint4*>(o + 8) = make_uint4(h[4], h[5], h[6], h[7]);
        }
    }
}

// ---------------------------------------------------------------------------
// route_kernel: grid = B, 320 threads = 10 warps. Lane = h*16 + cc:
// h = d-half, cc = class (active cc<10). Warp w owns capsules i = s*10 + w.
// All softmax exchange is warp-internal (shfls); 2 block barriers / iteration.
// ---------------------------------------------------------------------------
__global__ __launch_bounds__(320, 2) void route_kernel(float* __restrict__ out)
{
    const int b    = blockIdx.x;
    const int t    = threadIdx.x;
    const int w    = t >> 5;
    const int lane = t & 31;
    const int h    = lane >> 4;          // d-half
    const int cc   = lane & 15;          // class slot (0..15; active <10)
    const bool act = (cc < CCL);
    const int ccl  = act ? cc : (CCL - 1);   // clamped for loads

    __shared__ float buf[10][CCL][DOV];      // per-warp partial s: 6400 B
    __shared__ float vbuf[CCL][DOV + 2];     // running vacc

    const __half* base = g_uhat + (size_t)b * (ICAP * CCL * DOV)
                                + (size_t)ccl * DOV + h * 8;
    const int nsteps = (w < 2) ? 116 : 115;  // capsules i = s*10 + w

    // reduction-thread persistent state (threads 0..159 = warps 0..4)
    const int rc = t >> 4, rd = t & 15;
    float vacc_r = 0.0f;

    float vr[8];
    float sac[8];

    #pragma unroll 1
    for (int it = 0; it < 3; it++) {
        #pragma unroll
        for (int j = 0; j < 8; j++) sac[j] = 0.0f;

        int i = w;
        uint4 cur = *reinterpret_cast<const uint4*>(
            base + (size_t)i * (CCL * DOV));

        for (int s = 0; s < nsteps; s++) {
            const int inx = (s + 1 < nsteps) ? (i + 10) : i;
            uint4 nxt = *reinterpret_cast<const uint4*>(
                base + (size_t)inx * (CCL * DOV));

            float u[8];
            {
                const __half2* hc = reinterpret_cast<const __half2*>(&cur);
                #pragma unroll
                for (int q = 0; q < 4; q++) {
                    float2 f = __half22float2(hc[q]);
                    u[2 * q] = f.x; u[2 * q + 1] = f.y;
                }
            }

            float wgt;
            if (it == 0) {
                wgt = 0.1f;   // softmax of zeros over 10 classes
            } else {
                // half-dot, tree-ish
                float da = fmaf(u[1], vr[1], u[0] * vr[0]);
                da = fmaf(u[2], vr[2], da);
                da = fmaf(u[3], vr[3], da);
                float db = fmaf(u[5], vr[5], u[4] * vr[4]);
                db = fmaf(u[6], vr[6], db);
                db = fmaf(u[7], vr[7], db);
                float dp = da + db;
                dp += __shfl_xor_sync(0xffffffffu, dp, 16);  // full <u, vacc>
                // |logit| bounded (~35): exp safe in fp32
                float e = act ? __expf(dp) : 0.0f;
                float Z = e;
                #pragma unroll
                for (int off = 1; off < 16; off <<= 1)
                    Z += __shfl_xor_sync(0xffffffffu, Z, off);
                wgt = __fdividef(e, Z);   // cc>=10: e=0 -> wgt=0
            }

            #pragma unroll
            for (int j = 0; j < 8; j++) sac[j] = fmaf(wgt, u[j], sac[j]);

            cur = nxt; i += 10;
        }

        // ---- cross-warp s reduction (2 barriers per iteration)
        if (act) {
            #pragma unroll
            for (int j = 0; j < 8; j++) buf[w][cc][h * 8 + j] = sac[j];
        }
        __syncthreads();

        if (t < 160) {   // warps 0..4 fully inside: shfls non-divergent
            float s = 0.0f;
            #pragma unroll
            for (int ww = 0; ww < 10; ww++) s += buf[ww][rc][rd];
            float sq = s * s;
            #pragma unroll
            for (int off = 1; off < 16; off <<= 1)
                sq += __shfl_xor_sync(0xffffffffu, sq, off);
            float scale = __fdividef(sqrtf(sq), 1.0f + sq);
            if (it == 2) {
                out[(size_t)b * (CCL * DOV) + rc * DOV + rd] = s * scale;
            } else {
                vacc_r += s * scale;
                vbuf[rc][rd] = vacc_r;
            }
        }
        __syncthreads();

        if (it < 2) {
            #pragma unroll
            for (int j = 0; j < 8; j++) vr[j] = vbuf[ccl][h * 8 + j];
        }
    }
}

// ---------------------------------------------------------------------------
extern "C" void kernel_launch(void* const* d_in, const int* in_sizes, int n_in,
                              void* d_out, int out_size)
{
    const float* x = (const float*)d_in[0];
    const float* W = (const float*)d_in[1];
    if (in_sizes[0] == CCL * ICAP * DOV * DIV) {  // defensively identify by size
        const float* t = x; x = W; W = t;
    }
    float* out = (float*)d_out;

    uhat_kernel<<<NTIL * (BSZ / BCH), 256>>>(x, W);
    route_kernel<<<BSZ, 320>>>(out);
}